// round 17
// baseline (speedup 1.0000x reference)
#include <cuda_runtime.h>
#include <cuda_bf16.h>
#include <mma.h>
#include <cstdint>

using namespace nvcuda;

#define N_NODES 50000
#define N_EDGES 800000
#define D       64
#define CAP     64         // bucket capacity per node (max degree ~35 for this input)
#define OVF_MAX 4096

#define DTHREADS 256       // dense: 8 warps
#define DTILE    64        // rows per dense CTA
#define LDA      72        // bf16 row stride (mult of 8; 144B -> conflict-free ldmatrix)

// smem byte offsets for dense_tc (dynamic, 37120B -> fits default 48KB)
#define SM_AH    0                         // 64 x 72 bf16 = 9216
#define SM_AL    9216                      // 64 x 72 bf16
#define SM_BH    18432                     // 64 x 72 bf16
#define SM_BL    27648                     // 64 x 72 bf16
#define SM_BIAS  36864                     // 64 f32 = 256
#define SM_TOTAL 37120
// output staging reuses [SM_AH, SM_AH+16384) as float[64][64]

// Scratch (__device__ globals; zero-initialized at module load).
// Invariants restored every call: g_cnt zeroed by gather, g_ovf_cnt by reset.
__device__ int  g_cnt[N_NODES];
__device__ int2 g_edge[N_NODES * CAP];   // bucket slots: {src, float_as_int(w)}
__device__ int  g_ovf_cnt;
__device__ int4 g_ovf[OVF_MAX];          // {dst, src, w_bits, pad} overflow spill
__device__ float g_neigh[N_NODES * D];

// ---------------------------------------------------------------------------
// K0: tiny reset (keeps dense in the ncu capture slot)
// ---------------------------------------------------------------------------
__global__ void reset_kernel() {
    if (threadIdx.x == 0 && blockIdx.x == 0) g_ovf_cnt = 0;
}

// ---------------------------------------------------------------------------
// K1: bucket-scatter edges (R7 configuration: 8 edges/thread, interleaved).
// ---------------------------------------------------------------------------
__device__ __forceinline__ void bucket_put(int d, int s, float w) {
    int p = atomicAdd(&g_cnt[d], 1);
    if (p < CAP) {
        g_edge[d * CAP + p] = make_int2(s, __float_as_int(w));
    } else {
        int o = atomicAdd(&g_ovf_cnt, 1);
        if (o < OVF_MAX) g_ovf[o] = make_int4(d, s, __float_as_int(w), 0);
    }
}

__global__ void bucket_kernel(const int4*   __restrict__ src4,
                              const int4*   __restrict__ dst4,
                              const float4* __restrict__ w4) {
    int t = blockIdx.x * blockDim.x + threadIdx.x;
    int base = t * 2;
    const int NQ = N_EDGES / 4;
#pragma unroll
    for (int g = 0; g < 2; g++) {
        int q = base + g;
        if (q < NQ) {
            int4   s = src4[q];
            int4   d = dst4[q];
            float4 w = w4[q];
            bucket_put(d.x, s.x, w.x);
            bucket_put(d.y, s.y, w.y);
            bucket_put(d.z, s.z, w.z);
            bucket_put(d.w, s.w, w.w);
        }
    }
}

// ---------------------------------------------------------------------------
// K2: gather v2 (unchanged from R14) — 2 edges per warp-load via LDG.128.
// ---------------------------------------------------------------------------
#define GW 8
__global__ __launch_bounds__(GW * 32)
void gather_kernel(const float* __restrict__ h) {
    __shared__ int2 sE[GW][32];
    int wslot = threadIdx.x >> 5;
    int warp  = (blockIdx.x * blockDim.x + threadIdx.x) >> 5;
    int lane  = threadIdx.x & 31;
    if (warp >= N_NODES) return;

    int cnt = g_cnt[warp];
    int m   = min(cnt, CAP);
    const int2* bucket = g_edge + warp * CAP;

    const int half = lane >> 4;
    const int hl   = lane & 15;

    float4 acc = make_float4(0.f, 0.f, 0.f, 0.f);
    const float* hq = h + 4 * hl;

    for (int e0 = 0; e0 < m; e0 += 32) {
        int n = min(32, m - e0);
        if (lane < n) sE[wslot][lane] = bucket[e0 + lane];
        __syncwarp();

        int j = 0;
        for (; j + 8 <= n; j += 8) {
            float4 hv[4];
            float  ww[4];
#pragma unroll
            for (int q = 0; q < 4; q++) {
                int2 e = sE[wslot][j + 2 * q + half];
                ww[q] = __int_as_float(e.y);
                hv[q] = *reinterpret_cast<const float4*>(hq + (size_t)e.x * D);
            }
#pragma unroll
            for (int q = 0; q < 4; q++) {
                acc.x = fmaf(ww[q], hv[q].x, acc.x);
                acc.y = fmaf(ww[q], hv[q].y, acc.y);
                acc.z = fmaf(ww[q], hv[q].z, acc.z);
                acc.w = fmaf(ww[q], hv[q].w, acc.w);
            }
        }
        for (; j < n; j += 2) {
            int idx = j + half;
            if (idx < n) {
                int2 e = sE[wslot][idx];
                float wv = __int_as_float(e.y);
                float4 hv = *reinterpret_cast<const float4*>(hq + (size_t)e.x * D);
                acc.x = fmaf(wv, hv.x, acc.x);
                acc.y = fmaf(wv, hv.y, acc.y);
                acc.z = fmaf(wv, hv.z, acc.z);
                acc.w = fmaf(wv, hv.w, acc.w);
            }
        }
        __syncwarp();
    }

    if (cnt > CAP && half == 0) {
        int oc = min(g_ovf_cnt, OVF_MAX);
        for (int i = 0; i < oc; i++) {
            int4 e = g_ovf[i];
            if (e.x == warp) {
                float wv = __int_as_float(e.z);
                float4 hv = *reinterpret_cast<const float4*>(hq + (size_t)e.y * D);
                acc.x = fmaf(wv, hv.x, acc.x);
                acc.y = fmaf(wv, hv.y, acc.y);
                acc.z = fmaf(wv, hv.z, acc.z);
                acc.w = fmaf(wv, hv.w, acc.w);
            }
        }
    }

    acc.x += __shfl_xor_sync(0xffffffffu, acc.x, 16);
    acc.y += __shfl_xor_sync(0xffffffffu, acc.y, 16);
    acc.z += __shfl_xor_sync(0xffffffffu, acc.z, 16);
    acc.w += __shfl_xor_sync(0xffffffffu, acc.w, 16);

    if (half == 0)
        *reinterpret_cast<float4*>(g_neigh + (size_t)warp * D + 4 * hl) = acc;
    if (lane == 0) g_cnt[warp] = 0;
}

// ---------------------------------------------------------------------------
// K3: dense via wmma bf16 split (3-pass), 64-row tiles (grid 782).
// Warp w owns rows [16*(w>>1), +16) x cols [32*(w&1), +32): 2 acc frags.
// Per part (K=64): stage A(64x64)+W(64x64) -> hi/lo bf16 (stride 72), then
// 4 k-steps x 2 col-tiles x (ah*bh + ah*bl + al*bh), fp32 acc.
// Error: dropped al*bl ~2^-16 relative -> rel_err ~5e-6 << 1e-3 (measured R16).
// ---------------------------------------------------------------------------
__global__ __launch_bounds__(DTHREADS)
void dense_tc_kernel(const float* __restrict__ h,
                     const float* __restrict__ Ws, const float* __restrict__ bs,
                     const float* __restrict__ Wn, const float* __restrict__ bn,
                     float* __restrict__ out) {
    extern __shared__ __align__(16) char smem[];
    __nv_bfloat16* aH = reinterpret_cast<__nv_bfloat16*>(smem + SM_AH);
    __nv_bfloat16* aL = reinterpret_cast<__nv_bfloat16*>(smem + SM_AL);
    __nv_bfloat16* bH = reinterpret_cast<__nv_bfloat16*>(smem + SM_BH);
    __nv_bfloat16* bL = reinterpret_cast<__nv_bfloat16*>(smem + SM_BL);
    float*         sB = reinterpret_cast<float*>(smem + SM_BIAS);
    float*         stage = reinterpret_cast<float*>(smem + SM_AH);  // reuse

    const int tid = threadIdx.x;
    const int wid = tid >> 5;
    const int rs  = wid >> 1;          // row strip: rows [16rs, 16rs+16)
    const int ch  = wid & 1;           // col half:  cols [32ch, 32ch+32)
    const int rowBase = blockIdx.x * DTILE;

    if (tid < 64) sB[tid] = bs[tid] + bn[tid];

    wmma::fragment<wmma::accumulator, 16, 16, 16, float> acc[2];
#pragma unroll
    for (int n = 0; n < 2; n++) wmma::fill_fragment(acc[n], 0.f);

#pragma unroll
    for (int part = 0; part < 2; part++) {
        const float* xsrc = part ? g_neigh : h;
        const float* wsrc = part ? Wn : Ws;

        __syncthreads();   // previous part's mma reads complete

        // Stage A: 64 rows x 64 k -> hi/lo bf16 (coalesced float4 reads)
#pragma unroll
        for (int p = 0; p < 4; p++) {
            int f  = tid + DTHREADS * p;     // 0..1023
            int r  = f >> 4;                 // row 0..63
            int k0 = (f & 15) * 4;
            int rr = rowBase + r;
            float4 v = make_float4(0.f, 0.f, 0.f, 0.f);
            if (rr < N_NODES)
                v = *reinterpret_cast<const float4*>(xsrc + (size_t)rr * D + k0);
            float vv[4] = {v.x, v.y, v.z, v.w};
#pragma unroll
            for (int i = 0; i < 4; i++) {
                __nv_bfloat16 hi = __float2bfloat16(vv[i]);
                __nv_bfloat16 lo = __float2bfloat16(vv[i] - __bfloat162float(hi));
                aH[r * LDA + k0 + i] = hi;
                aL[r * LDA + k0 + i] = lo;
            }
        }

        // Stage B: W [j=64][k=64] -> hi/lo bf16 rows (col-major B: (k,n)=b[n*LDA+k])
#pragma unroll
        for (int p = 0; p < 4; p++) {
            int f  = tid + DTHREADS * p;     // 0..1023
            int j  = f >> 4;
            int k0 = (f & 15) * 4;
            float4 v = *reinterpret_cast<const float4*>(wsrc + j * 64 + k0);
            float vv[4] = {v.x, v.y, v.z, v.w};
#pragma unroll
            for (int i = 0; i < 4; i++) {
                __nv_bfloat16 hi = __float2bfloat16(vv[i]);
                __nv_bfloat16 lo = __float2bfloat16(vv[i] - __bfloat162float(hi));
                bH[j * LDA + k0 + i] = hi;
                bL[j * LDA + k0 + i] = lo;
            }
        }
        __syncthreads();

        const __nv_bfloat16* arow = aH + rs * 16 * LDA;
        const __nv_bfloat16* arol = aL + rs * 16 * LDA;

#pragma unroll
        for (int ks = 0; ks < 4; ks++) {
            wmma::fragment<wmma::matrix_a, 16, 16, 16, __nv_bfloat16, wmma::row_major> ah, al;
            wmma::load_matrix_sync(ah, arow + ks * 16, LDA);
            wmma::load_matrix_sync(al, arol + ks * 16, LDA);
#pragma unroll
            for (int n = 0; n < 2; n++) {
                int colTile = ch * 32 + n * 16;
                wmma::fragment<wmma::matrix_b, 16, 16, 16, __nv_bfloat16, wmma::col_major> bh, bl;
                wmma::load_matrix_sync(bh, bH + colTile * LDA + ks * 16, LDA);
                wmma::load_matrix_sync(bl, bL + colTile * LDA + ks * 16, LDA);
                wmma::mma_sync(acc[n], ah, bh, acc[n]);
                wmma::mma_sync(acc[n], ah, bl, acc[n]);
                wmma::mma_sync(acc[n], al, bh, acc[n]);
            }
        }
    }

    // Epilogue: stage fp32 result (reuses A smem), bias + relu, coalesced out
    __syncthreads();
#pragma unroll
    for (int n = 0; n < 2; n++)
        wmma::store_matrix_sync(stage + rs * 16 * 64 + ch * 32 + n * 16, acc[n], 64,
                                wmma::mem_row_major);
    __syncthreads();

#pragma unroll
    for (int p = 0; p < 4; p++) {
        int f  = tid + DTHREADS * p;         // 0..1023
        int r  = f >> 4;                     // row 0..63
        int c4 = (f & 15) * 4;
        int rr = rowBase + r;
        if (rr < N_NODES) {
            float4 v = *reinterpret_cast<const float4*>(stage + r * 64 + c4);
            float4 o;
            o.x = fmaxf(v.x + sB[c4 + 0], 0.f);
            o.y = fmaxf(v.y + sB[c4 + 1], 0.f);
            o.z = fmaxf(v.z + sB[c4 + 2], 0.f);
            o.w = fmaxf(v.w + sB[c4 + 3], 0.f);
            *reinterpret_cast<float4*>(out + (size_t)rr * D + c4) = o;
        }
    }
}

// ---------------------------------------------------------------------------
// kernel_launch
//   0: h [N,D] f32   1: edge_src [E] i32   2: edge_dst [E] i32   3: edge_w [E] f32
//   4: W_self [D,D]  5: b_self [D]         6: W_neigh [D,D]      7: b_neigh [D]
// ---------------------------------------------------------------------------
extern "C" void kernel_launch(void* const* d_in, const int* in_sizes, int n_in,
                              void* d_out, int out_size) {
    const float* h        = (const float*)d_in[0];
    const int*   edge_src = (const int*)  d_in[1];
    const int*   edge_dst = (const int*)  d_in[2];
    const float* edge_w   = (const float*)d_in[3];
    const float* W_self   = (const float*)d_in[4];
    const float* b_self   = (const float*)d_in[5];
    const float* W_neigh  = (const float*)d_in[6];
    const float* b_neigh  = (const float*)d_in[7];
    float* out = (float*)d_out;

    reset_kernel<<<1, 32>>>();

    {
        int threadsTotal = N_EDGES / 8;
        int blocks = (threadsTotal + 255) / 256;
        bucket_kernel<<<blocks, 256>>>((const int4*)edge_src, (const int4*)edge_dst,
                                       (const float4*)edge_w);
    }

    {
        int blocks = (N_NODES + GW - 1) / GW;
        gather_kernel<<<blocks, GW * 32>>>(h);
    }

    {
        int blocks = (N_NODES + DTILE - 1) / DTILE;
        dense_tc_kernel<<<blocks, DTHREADS, SM_TOTAL>>>(h, W_self, b_self,
                                                        W_neigh, b_neigh, out);
    }
}